// round 2
// baseline (speedup 1.0000x reference)
#include <cuda_runtime.h>
#include <cuda_bf16.h>
#include <stdint.h>
#include <math.h>

#define LAYERS_   10
#define NL_       40
#define RC_       32
#define DC_       32
#define SC_       256
#define EC_       256
#define CL_       256
#define B_        8
#define T_        16384
#define BT_       131072   /* B_*T_ */

// ---------------- scratch (static device globals; no allocations) -------------
__device__ float g_h[32 * BT_];                       // residual state, [c][BT]
__device__ float g_z[167772160];                      // 40*32*BT, [layer][c][BT]
__device__ float g_skip[SC_ * BT_];                   // [c][BT]
__device__ float g_out1[EC_ * BT_];                   // [c][BT]
__device__ float g_skipb[SC_];

// ---------------- small helpers ----------------
__device__ __forceinline__ unsigned f2tf(float x) {
    unsigned r;
    asm("cvt.rna.tf32.f32 %0, %1;" : "=r"(r) : "f"(x));
    return r;
}
__device__ __forceinline__ void mma8(float* d, const unsigned* a, const unsigned* b) {
    asm volatile(
        "mma.sync.aligned.m16n8k8.row.col.f32.tf32.tf32.f32 "
        "{%0,%1,%2,%3},{%4,%5,%6,%7},{%8,%9},{%0,%1,%2,%3};\n"
        : "+f"(d[0]), "+f"(d[1]), "+f"(d[2]), "+f"(d[3])
        : "r"(a[0]), "r"(a[1]), "r"(a[2]), "r"(a[3]), "r"(b[0]), "r"(b[1]));
}

// predicated/vector load of 4 consecutive tokens at offset -dil
__device__ __forceinline__ float4 ldprev(const float* __restrict__ row, int i0,
                                         int tmod, int dil) {
    if (dil >= 4 && tmod >= dil) {
        return *(const float4*)(row + (i0 - dil));
    }
    float4 r;
    r.x = (tmod + 0 >= dil) ? row[i0 + 0 - dil] : 0.f;
    r.y = (tmod + 1 >= dil) ? row[i0 + 1 - dil] : 0.f;
    r.z = (tmod + 2 >= dil) ? row[i0 + 2 - dil] : 0.f;
    r.w = (tmod + 3 >= dil) ? row[i0 + 3 - dil] : 0.f;
    return r;
}

// ---------------- bias reduction for skip ----------------
__global__ void k_bias(const float* __restrict__ skip_b) {
    int o = threadIdx.x;
    float s = 0.f;
#pragma unroll 1
    for (int i = 0; i < NL_; i++) s += skip_b[i * SC_ + o];
    g_skipb[o] = s;
}

// ---------------- input 1x1 conv: x[8,256,16384] -> h[32][BT] ----------------
// thread = 4 tokens x 8 output channels; 4 output-groups per block (256 tokens/block)
__global__ __launch_bounds__(256, 2) void k_input(const float* __restrict__ x,
                                                  const float* __restrict__ w_in,
                                                  const float* __restrict__ b_in) {
    __shared__ __align__(16) float ws[256 * 32];   // [c][rc]
    __shared__ float bs[32];
    int tid = threadIdx.x;
    for (int e = tid; e < 256 * 32; e += 256) {
        int c = e >> 5, rc = e & 31;
        ws[e] = w_in[rc * 256 + c];
    }
    if (tid < 32) bs[tid] = b_in[tid];
    __syncthreads();

    int og = tid >> 6;       // 0..3
    int tg = tid & 63;       // 64 token-groups
    int ob = og * 8;
    int i0 = blockIdx.x * 256 + tg * 4;
    int b0 = i0 >> 14, t0 = i0 & (T_ - 1);
    const float* xb = x + (size_t)b0 * 256 * T_ + t0;

    float acc[8][4];
#pragma unroll
    for (int o = 0; o < 8; o++)
#pragma unroll
        for (int q = 0; q < 4; q++) acc[o][q] = 0.f;

    float4 xv = *(const float4*)xb;
#pragma unroll 1
    for (int c = 0; c < 256; c++) {
        int cn = (c < 255) ? c + 1 : 255;
        float4 nxv = *(const float4*)(xb + (size_t)cn * T_);
        float w[8];
        *(float4*)&w[0] = *(const float4*)&ws[c * 32 + ob];
        *(float4*)&w[4] = *(const float4*)&ws[c * 32 + ob + 4];
#pragma unroll
        for (int o = 0; o < 8; o++) {
            acc[o][0] = fmaf(w[o], xv.x, acc[o][0]);
            acc[o][1] = fmaf(w[o], xv.y, acc[o][1]);
            acc[o][2] = fmaf(w[o], xv.z, acc[o][2]);
            acc[o][3] = fmaf(w[o], xv.w, acc[o][3]);
        }
        xv = nxv;
    }
#pragma unroll
    for (int o = 0; o < 8; o++) {
        float b = bs[ob + o];
        float4 v = make_float4(acc[o][0] + b, acc[o][1] + b, acc[o][2] + b, acc[o][3] + b);
        *(float4*)(g_h + (size_t)(ob + o) * BT_ + i0) = v;
    }
}

// ---------------- per-layer z = tanh(filt)*sigmoid(gate) ----------------
// thread = 4 tokens x 8 outputs (filt AND gate); 4 output-groups; 256 tokens/block
__global__ __launch_bounds__(256, 2) void k_z(const float* __restrict__ filt_w,
                                              const float* __restrict__ filt_b,
                                              const float* __restrict__ gate_w,
                                              const float* __restrict__ gate_b,
                                              int layer, int dil) {
    __shared__ __align__(16) float s_fw0[1024], s_fw1[1024], s_gw0[1024], s_gw1[1024];  // [c][o]
    __shared__ float s_fb[32], s_gb[32];
    int tid = threadIdx.x;
    {
        const float* fwL = filt_w + layer * 2048;
        const float* gwL = gate_w + layer * 2048;
        for (int e = tid; e < 1024; e += 256) {
            int c = e >> 5, o = e & 31;
            int src = (o * 32 + c) * 2;
            s_fw0[c * 32 + o] = fwL[src];
            s_fw1[c * 32 + o] = fwL[src + 1];
            s_gw0[c * 32 + o] = gwL[src];
            s_gw1[c * 32 + o] = gwL[src + 1];
        }
        if (tid < 32) {
            s_fb[tid] = filt_b[layer * 32 + tid];
            s_gb[tid] = gate_b[layer * 32 + tid];
        }
    }
    __syncthreads();

    int og = tid >> 6;
    int tg = tid & 63;
    int ob = og * 8;
    int i0 = blockIdx.x * 256 + tg * 4;
    int tmod = i0 & (T_ - 1);

    float fa[8][4], ga[8][4];
#pragma unroll
    for (int o = 0; o < 8; o++)
#pragma unroll
        for (int q = 0; q < 4; q++) { fa[o][q] = 0.f; ga[o][q] = 0.f; }

    float4 hc = *(const float4*)(g_h + i0);
    float4 hp = ldprev(g_h, i0, tmod, dil);

#pragma unroll 1
    for (int c = 0; c < 32; c++) {
        int cn = (c < 31) ? c + 1 : 31;
        const float* nrow = g_h + (size_t)cn * BT_;
        float4 nhc = *(const float4*)(nrow + i0);
        float4 nhp = ldprev(nrow, i0, tmod, dil);

        float wf0[8], wf1[8];
        *(float4*)&wf0[0] = *(const float4*)&s_fw0[c * 32 + ob];
        *(float4*)&wf0[4] = *(const float4*)&s_fw0[c * 32 + ob + 4];
        *(float4*)&wf1[0] = *(const float4*)&s_fw1[c * 32 + ob];
        *(float4*)&wf1[4] = *(const float4*)&s_fw1[c * 32 + ob + 4];
#pragma unroll
        for (int o = 0; o < 8; o++) {
            fa[o][0] = fmaf(wf1[o], hc.x, fmaf(wf0[o], hp.x, fa[o][0]));
            fa[o][1] = fmaf(wf1[o], hc.y, fmaf(wf0[o], hp.y, fa[o][1]));
            fa[o][2] = fmaf(wf1[o], hc.z, fmaf(wf0[o], hp.z, fa[o][2]));
            fa[o][3] = fmaf(wf1[o], hc.w, fmaf(wf0[o], hp.w, fa[o][3]));
        }
        float wg0[8], wg1[8];
        *(float4*)&wg0[0] = *(const float4*)&s_gw0[c * 32 + ob];
        *(float4*)&wg0[4] = *(const float4*)&s_gw0[c * 32 + ob + 4];
        *(float4*)&wg1[0] = *(const float4*)&s_gw1[c * 32 + ob];
        *(float4*)&wg1[4] = *(const float4*)&s_gw1[c * 32 + ob + 4];
#pragma unroll
        for (int o = 0; o < 8; o++) {
            ga[o][0] = fmaf(wg1[o], hc.x, fmaf(wg0[o], hp.x, ga[o][0]));
            ga[o][1] = fmaf(wg1[o], hc.y, fmaf(wg0[o], hp.y, ga[o][1]));
            ga[o][2] = fmaf(wg1[o], hc.z, fmaf(wg0[o], hp.z, ga[o][2]));
            ga[o][3] = fmaf(wg1[o], hc.w, fmaf(wg0[o], hp.w, ga[o][3]));
        }
        hc = nhc;
        hp = nhp;
    }

#pragma unroll
    for (int o = 0; o < 8; o++) {
        float fb = s_fb[ob + o], gb = s_gb[ob + o];
        float4 zv;
        {
            float fx = fa[o][0] + fb;
            float ef = __expf(-2.f * fabsf(fx));
            float th = copysignf(__fdividef(1.f - ef, 1.f + ef), fx);
            float sg = __fdividef(1.f, 1.f + __expf(-(ga[o][0] + gb)));
            zv.x = th * sg;
        }
        {
            float fx = fa[o][1] + fb;
            float ef = __expf(-2.f * fabsf(fx));
            float th = copysignf(__fdividef(1.f - ef, 1.f + ef), fx);
            float sg = __fdividef(1.f, 1.f + __expf(-(ga[o][1] + gb)));
            zv.y = th * sg;
        }
        {
            float fx = fa[o][2] + fb;
            float ef = __expf(-2.f * fabsf(fx));
            float th = copysignf(__fdividef(1.f - ef, 1.f + ef), fx);
            float sg = __fdividef(1.f, 1.f + __expf(-(ga[o][2] + gb)));
            zv.z = th * sg;
        }
        {
            float fx = fa[o][3] + fb;
            float ef = __expf(-2.f * fabsf(fx));
            float th = copysignf(__fdividef(1.f - ef, 1.f + ef), fx);
            float sg = __fdividef(1.f, 1.f + __expf(-(ga[o][3] + gb)));
            zv.w = th * sg;
        }
        *(float4*)(g_z + ((size_t)layer * 32 + ob + o) * BT_ + i0) = zv;
    }
}

// ---------------- per-layer residual update: h += conv(z, res_w, d) ----------------
__global__ __launch_bounds__(256, 2) void k_res(const float* __restrict__ res_w,
                                                const float* __restrict__ res_b,
                                                int layer, int dil) {
    __shared__ __align__(16) float s_w0[1024], s_w1[1024];  // [c][o]
    __shared__ float s_b[32];
    int tid = threadIdx.x;
    {
        const float* wL = res_w + layer * 2048;
        for (int e = tid; e < 1024; e += 256) {
            int c = e >> 5, o = e & 31;
            int src = (o * 32 + c) * 2;
            s_w0[c * 32 + o] = wL[src];
            s_w1[c * 32 + o] = wL[src + 1];
        }
        if (tid < 32) s_b[tid] = res_b[layer * 32 + tid];
    }
    __syncthreads();

    int og = tid >> 6;
    int tg = tid & 63;
    int ob = og * 8;
    int i0 = blockIdx.x * 256 + tg * 4;
    int tmod = i0 & (T_ - 1);

    const float* zL = g_z + (size_t)layer * 32 * BT_;

    float acc[8][4];
#pragma unroll
    for (int o = 0; o < 8; o++)
#pragma unroll
        for (int q = 0; q < 4; q++) acc[o][q] = 0.f;

    float4 zc = *(const float4*)(zL + i0);
    float4 zp = ldprev(zL, i0, tmod, dil);

#pragma unroll 1
    for (int c = 0; c < 32; c++) {
        int cn = (c < 31) ? c + 1 : 31;
        const float* nrow = zL + (size_t)cn * BT_;
        float4 nzc = *(const float4*)(nrow + i0);
        float4 nzp = ldprev(nrow, i0, tmod, dil);

        float w0[8], w1[8];
        *(float4*)&w0[0] = *(const float4*)&s_w0[c * 32 + ob];
        *(float4*)&w0[4] = *(const float4*)&s_w0[c * 32 + ob + 4];
        *(float4*)&w1[0] = *(const float4*)&s_w1[c * 32 + ob];
        *(float4*)&w1[4] = *(const float4*)&s_w1[c * 32 + ob + 4];
#pragma unroll
        for (int o = 0; o < 8; o++) {
            acc[o][0] = fmaf(w1[o], zc.x, fmaf(w0[o], zp.x, acc[o][0]));
            acc[o][1] = fmaf(w1[o], zc.y, fmaf(w0[o], zp.y, acc[o][1]));
            acc[o][2] = fmaf(w1[o], zc.z, fmaf(w0[o], zp.z, acc[o][2]));
            acc[o][3] = fmaf(w1[o], zc.w, fmaf(w0[o], zp.w, acc[o][3]));
        }
        zc = nzc;
        zp = nzp;
    }

#pragma unroll
    for (int o = 0; o < 8; o++) {
        float b = s_b[ob + o];
        float* hrow = g_h + (size_t)(ob + o) * BT_ + i0;
        float4 hv = *(const float4*)hrow;
        hv.x += acc[o][0] + b;
        hv.y += acc[o][1] + b;
        hv.z += acc[o][2] + b;
        hv.w += acc[o][3] + b;
        *(float4*)hrow = hv;
    }
}

// ---------------- deferred skip GEMM: skip = W[256x2560] * Zgather + bias ----------------
// tf32 mma: CTA tile 128(M) x 128(N tokens); 8 warps as 4x2; warp tile 32x64.
#define SA_STR 36
#define SB_STR 136

__global__ __launch_bounds__(256) void k_skip(const float* __restrict__ skip_w) {
    __shared__ unsigned smem_u[128 * SA_STR + 32 * SB_STR];  // 8960 words
    unsigned* sA = smem_u;
    unsigned* sB = smem_u + 128 * SA_STR;

    int tid = threadIdx.x;
    int warp = tid >> 5, lane = tid & 31;
    int grp = lane >> 2, tig = lane & 3;
    int m_base = blockIdx.y * 128;
    int t0 = blockIdx.x * 128;
    int m_off = (warp >> 1) * 32;
    int n_off = (warp & 1) * 64;

    float acc[2][8][4];
#pragma unroll
    for (int mf = 0; mf < 2; mf++)
#pragma unroll
        for (int nf = 0; nf < 8; nf++)
#pragma unroll
            for (int q = 0; q < 4; q++) acc[mf][nf][q] = 0.f;

#pragma unroll 1
    for (int step = 0; step < 2 * NL_; step++) {
        int li = step >> 1;
        int tap = step & 1;
        int dil = 1 << (li % LAYERS_);
        int shift = (tap == 0) ? dil : 0;

        // stage A: weights [128 out][32 in] for (li, tap)
#pragma unroll 4
        for (int j = 0; j < 16; j++) {
            int e = tid + j * 256;
            int r = e >> 5, c = e & 31;
            float w = skip_w[(((size_t)li * SC_ + m_base + r) * 32 + c) * 2 + tap];
            sA[r * SA_STR + c] = f2tf(w);
        }
        // stage B: z [32 in][128 tokens], shifted by dilation, zero-padded per batch
#pragma unroll 4
        for (int j = 0; j < 16; j++) {
            int e = tid + j * 256;
            int c = e >> 7, t = e & 127;
            int g = t0 + t;
            float v = 0.f;
            if ((g & (T_ - 1)) >= shift) v = g_z[((size_t)li * 32 + c) * BT_ + g - shift];
            sB[c * SB_STR + t] = f2tf(v);
        }
        __syncthreads();

#pragma unroll
        for (int kc = 0; kc < 32; kc += 8) {
            unsigned a[2][4], b[8][2];
#pragma unroll
            for (int mf = 0; mf < 2; mf++) {
                int r = m_off + mf * 16 + grp;
                a[mf][0] = sA[r * SA_STR + kc + tig];
                a[mf][1] = sA[(r + 8) * SA_STR + kc + tig];
                a[mf][2] = sA[r * SA_STR + kc + tig + 4];
                a[mf][3] = sA[(r + 8) * SA_STR + kc + tig + 4];
            }
#pragma unroll
            for (int nf = 0; nf < 8; nf++) {
                int cidx = n_off + nf * 8 + grp;
                b[nf][0] = sB[(kc + tig) * SB_STR + cidx];
                b[nf][1] = sB[(kc + tig + 4) * SB_STR + cidx];
            }
#pragma unroll
            for (int mf = 0; mf < 2; mf++)
#pragma unroll
                for (int nf = 0; nf < 8; nf++) mma8(acc[mf][nf], a[mf], b[nf]);
        }
        __syncthreads();
    }

#pragma unroll
    for (int mf = 0; mf < 2; mf++)
#pragma unroll
        for (int nf = 0; nf < 8; nf++) {
            int row0 = m_off + mf * 16 + grp;
            int col0 = n_off + nf * 8 + 2 * tig;
            float bias0 = g_skipb[m_base + row0];
            float bias1 = g_skipb[m_base + row0 + 8];
            size_t p0 = (size_t)(m_base + row0) * BT_ + t0 + col0;
            size_t p2 = (size_t)(m_base + row0 + 8) * BT_ + t0 + col0;
            g_skip[p0] = acc[mf][nf][0] + bias0;
            g_skip[p0 + 1] = acc[mf][nf][1] + bias0;
            g_skip[p2] = acc[mf][nf][2] + bias1;
            g_skip[p2 + 1] = acc[mf][nf][3] + bias1;
        }
}

// ---------------- end1 / end2 GEMMs (relu on input), STAGE=1: skip->out1, STAGE=2: out1->d_out^T
template <int STAGE>
__global__ __launch_bounds__(256) void k_end(const float* __restrict__ W,
                                             const float* __restrict__ bvec,
                                             float* __restrict__ dout) {
    __shared__ unsigned smem_u[128 * SA_STR + 32 * SB_STR];
    unsigned* sA = smem_u;
    unsigned* sB = smem_u + 128 * SA_STR;

    int tid = threadIdx.x;
    int warp = tid >> 5, lane = tid & 31;
    int grp = lane >> 2, tig = lane & 3;
    int m_base = blockIdx.y * 128;
    int t0 = blockIdx.x * 128;
    int m_off = (warp >> 1) * 32;
    int warp_n = warp & 1;
    int n_off = warp_n * 64;

    const float* gin = (STAGE == 1) ? g_skip : g_out1;

    float acc[2][8][4];
#pragma unroll
    for (int mf = 0; mf < 2; mf++)
#pragma unroll
        for (int nf = 0; nf < 8; nf++)
#pragma unroll
            for (int q = 0; q < 4; q++) acc[mf][nf][q] = 0.f;

#pragma unroll 1
    for (int step = 0; step < 8; step++) {
        int kc0 = step * 32;
#pragma unroll 4
        for (int j = 0; j < 16; j++) {
            int e = tid + j * 256;
            int r = e >> 5, c = e & 31;
            sA[r * SA_STR + c] = f2tf(W[(size_t)(m_base + r) * 256 + kc0 + c]);
        }
#pragma unroll 4
        for (int j = 0; j < 16; j++) {
            int e = tid + j * 256;
            int c = e >> 7, t = e & 127;
            float v = gin[(size_t)(kc0 + c) * BT_ + t0 + t];
            v = fmaxf(v, 0.f);  // relu on input (both stages)
            sB[c * SB_STR + t] = f2tf(v);
        }
        __syncthreads();
#pragma unroll
        for (int kc = 0; kc < 32; kc += 8) {
            unsigned a[2][4], b[8][2];
#pragma unroll
            for (int mf = 0; mf < 2; mf++) {
                int r = m_off + mf * 16 + grp;
                a[mf][0] = sA[r * SA_STR + kc + tig];
                a[mf][1] = sA[(r + 8) * SA_STR + kc + tig];
                a[mf][2] = sA[r * SA_STR + kc + tig + 4];
                a[mf][3] = sA[(r + 8) * SA_STR + kc + tig + 4];
            }
#pragma unroll
            for (int nf = 0; nf < 8; nf++) {
                int cidx = n_off + nf * 8 + grp;
                b[nf][0] = sB[(kc + tig) * SB_STR + cidx];
                b[nf][1] = sB[(kc + tig + 4) * SB_STR + cidx];
            }
#pragma unroll
            for (int mf = 0; mf < 2; mf++)
#pragma unroll
                for (int nf = 0; nf < 8; nf++) mma8(acc[mf][nf], a[mf], b[nf]);
        }
        __syncthreads();
    }

    if (STAGE == 1) {
        // channel-major write to g_out1
#pragma unroll
        for (int mf = 0; mf < 2; mf++)
#pragma unroll
            for (int nf = 0; nf < 8; nf++) {
                int row0 = m_off + mf * 16 + grp;
                int col0 = n_off + nf * 8 + 2 * tig;
                float bias0 = bvec[m_base + row0];
                float bias1 = bvec[m_base + row0 + 8];
                size_t p0 = (size_t)(m_base + row0) * BT_ + t0 + col0;
                size_t p2 = (size_t)(m_base + row0 + 8) * BT_ + t0 + col0;
                g_out1[p0] = acc[mf][nf][0] + bias0;
                g_out1[p0 + 1] = acc[mf][nf][1] + bias0;
                g_out1[p2] = acc[mf][nf][2] + bias1;
                g_out1[p2 + 1] = acc[mf][nf][3] + bias1;
            }
    } else {
        // transpose to token-major d_out[(token)*256 + ch] via shared memory
        float* ts = (float*)smem_u;  // [64 tokens][132]
#pragma unroll 1
        for (int half = 0; half < 2; half++) {
            __syncthreads();
            if (warp_n == half) {
#pragma unroll
                for (int mf = 0; mf < 2; mf++)
#pragma unroll
                    for (int nf = 0; nf < 8; nf++) {
                        int rowL = m_off + mf * 16 + grp;
                        int colL = nf * 8 + 2 * tig;  // 0..63 within half
                        float bias0 = bvec[m_base + rowL];
                        float bias1 = bvec[m_base + rowL + 8];
                        ts[colL * 132 + rowL] = acc[mf][nf][0] + bias0;
                        ts[(colL + 1) * 132 + rowL] = acc[mf][nf][1] + bias0;
                        ts[colL * 132 + rowL + 8] = acc[mf][nf][2] + bias1;
                        ts[(colL + 1) * 132 + rowL + 8] = acc[mf][nf][3] + bias1;
                    }
            }
            __syncthreads();
            // write 64 tokens x 128 channels, coalesced float4 per token row
#pragma unroll
            for (int pass = 0; pass < 8; pass++) {
                int tk = pass * 8 + (tid >> 5);
                float4 v = *(const float4*)&ts[tk * 132 + lane * 4];
                *(float4*)&dout[(size_t)(t0 + half * 64 + tk) * 256 + m_base + lane * 4] = v;
            }
        }
    }
}

// ---------------- host launcher ----------------
extern "C" void kernel_launch(void* const* d_in, const int* in_sizes, int n_in,
                              void* d_out, int out_size) {
    const float* x      = (const float*)d_in[0];
    const float* w_in   = (const float*)d_in[1];
    const float* b_in   = (const float*)d_in[2];
    const float* filt_w = (const float*)d_in[3];
    const float* filt_b = (const float*)d_in[4];
    const float* gate_w = (const float*)d_in[5];
    const float* gate_b = (const float*)d_in[6];
    const float* res_w  = (const float*)d_in[7];
    const float* res_b  = (const float*)d_in[8];
    const float* skip_w = (const float*)d_in[9];
    const float* skip_b = (const float*)d_in[10];
    const float* end1_w = (const float*)d_in[11];
    const float* end1_b = (const float*)d_in[12];
    const float* end2_w = (const float*)d_in[13];
    const float* end2_b = (const float*)d_in[14];
    float* out = (float*)d_out;

    k_bias<<<1, 256>>>(skip_b);
    k_input<<<BT_ / 256, 256>>>(x, w_in, b_in);

    for (int i = 0; i < NL_; i++) {
        int d = 1 << (i % LAYERS_);
        k_z<<<BT_ / 256, 256>>>(filt_w, filt_b, gate_w, gate_b, i, d);
        k_res<<<BT_ / 256, 256>>>(res_w, res_b, i, d);
    }

    dim3 gg(BT_ / 128, 2);
    k_skip<<<gg, 256>>>(skip_w);
    k_end<1><<<gg, 256>>>(end1_w, end1_b, nullptr);
    k_end<2><<<gg, 256>>>(end2_w, end2_b, out);
}

// round 4
// speedup vs baseline: 1.4223x; 1.4223x over previous
#include <cuda_runtime.h>
#include <cuda_bf16.h>
#include <stdint.h>
#include <math.h>

#define LAYERS_   10
#define NL_       40
#define RC_       32
#define DC_       32
#define SC_       256
#define EC_       256
#define CL_       256
#define B_        8
#define T_        16384
#define BT_       131072   /* B_*T_ */

// ---------------- scratch (static device globals; no allocations) -------------
__device__ float g_h[32 * BT_];                       // residual state, [c][BT]
__device__ float g_z[167772160];                      // 40*32*BT, [layer][c][BT] (tf32-rounded)
__device__ float g_skip[SC_ * BT_];                   // [c][BT]  relu(skip), tf32-rounded
__device__ float g_out1[EC_ * BT_];                   // [c][BT]  relu(out1), tf32-rounded
__device__ float g_skipb[SC_];
__device__ unsigned g_wA[786432];                     // packed tf32 weights, K-major

#define WOFF_SKIP 0
#define WOFF_E1   655360
#define WOFF_E2   720896

// ---------------- small helpers ----------------
__device__ __forceinline__ unsigned f2tf(float x) {
    unsigned r;
    asm("cvt.rna.tf32.f32 %0, %1;" : "=r"(r) : "f"(x));
    return r;
}
__device__ __forceinline__ float rtf(float x) {      // RN-round to tf32, as float
    return __uint_as_float(f2tf(x));
}
__device__ __forceinline__ void mma8(float* d, const unsigned* a, const unsigned* b) {
    asm volatile(
        "mma.sync.aligned.m16n8k8.row.col.f32.tf32.tf32.f32 "
        "{%0,%1,%2,%3},{%4,%5,%6,%7},{%8,%9},{%0,%1,%2,%3};\n"
        : "+f"(d[0]), "+f"(d[1]), "+f"(d[2]), "+f"(d[3])
        : "r"(a[0]), "r"(a[1]), "r"(a[2]), "r"(a[3]), "r"(b[0]), "r"(b[1]));
}

#define CP16(dst, src) asm volatile("cp.async.cg.shared.global [%0], [%1], 16;\n" :: "r"(dst), "l"(src))
#define CPCOMMIT()     asm volatile("cp.async.commit_group;\n")
#define CPWAIT1()      asm volatile("cp.async.wait_group 1;\n" ::: "memory")
#define CPWAIT0()      asm volatile("cp.async.wait_group 0;\n" ::: "memory")

// ---------------- bias reduction for skip ----------------
__global__ void k_bias(const float* __restrict__ skip_b) {
    int o = threadIdx.x;
    float s = 0.f;
#pragma unroll 1
    for (int i = 0; i < NL_; i++) s += skip_b[i * SC_ + o];
    g_skipb[o] = s;
}

// ---------------- pack all GEMM weights K-major as tf32 ----------------
__global__ void k_pack(const float* __restrict__ skip_w,
                       const float* __restrict__ e1w,
                       const float* __restrict__ e2w) {
    int idx = blockIdx.x * 256 + threadIdx.x;
    if (idx < WOFF_E1) {
        int k = idx >> 8, m = idx & 255;
        int li = k >> 6, tap = (k >> 5) & 1, c = k & 31;
        g_wA[idx] = f2tf(skip_w[((size_t)(li * 256 + m) * 32 + c) * 2 + tap]);
    } else if (idx < WOFF_E2) {
        int local = idx - WOFF_E1;
        int k = local >> 8, m = local & 255;
        g_wA[idx] = f2tf(e1w[m * 256 + k]);
    } else if (idx < 786432) {
        int local = idx - WOFF_E2;
        int k = local >> 8, m = local & 255;
        g_wA[idx] = f2tf(e2w[m * 256 + k]);
    }
}

// ---------------- input 1x1 conv: x[8,256,16384] -> h[32][BT] (R1 version) ----
__global__ __launch_bounds__(256) void k_input(const float* __restrict__ x,
                                               const float* __restrict__ w_in,
                                               const float* __restrict__ b_in) {
    __shared__ float ws[256 * 32];   // [c][rc]
    __shared__ float bs[32];
    int tid = threadIdx.x;
    for (int e = tid; e < 256 * 32; e += 256) {
        int c = e >> 5, rc = e & 31;
        ws[e] = w_in[rc * 256 + c];
    }
    if (tid < 32) bs[tid] = b_in[tid];
    __syncthreads();

    int i0 = blockIdx.x * 512 + tid;
    int i1 = i0 + 256;
    int b0 = i0 >> 14, t0 = i0 & (T_ - 1);
    int b1 = i1 >> 14, t1 = i1 & (T_ - 1);
    const float* x0 = x + (size_t)b0 * 256 * T_ + t0;
    const float* x1 = x + (size_t)b1 * 256 * T_ + t1;

    float a0[32], a1[32];
#pragma unroll
    for (int r = 0; r < 32; r++) { a0[r] = bs[r]; a1[r] = bs[r]; }

#pragma unroll 1
    for (int c = 0; c < 256; c++) {
        float xv0 = x0[(size_t)c * T_];
        float xv1 = x1[(size_t)c * T_];
        const float* w = &ws[c * 32];
#pragma unroll
        for (int r = 0; r < 32; r++) {
            a0[r] = fmaf(w[r], xv0, a0[r]);
            a1[r] = fmaf(w[r], xv1, a1[r]);
        }
    }
#pragma unroll
    for (int r = 0; r < 32; r++) {
        g_h[r * BT_ + i0] = a0[r];
        g_h[r * BT_ + i1] = a1[r];
    }
}

// ---------------- per-layer z = tanh(filt)*sigmoid(gate) (R1 version) --------
__global__ __launch_bounds__(256) void k_z(const float* __restrict__ filt_w,
                                           const float* __restrict__ filt_b,
                                           const float* __restrict__ gate_w,
                                           const float* __restrict__ gate_b,
                                           int layer, int dil) {
    __shared__ float s_fw0[1024], s_fw1[1024], s_gw0[1024], s_gw1[1024];  // [c][o]
    __shared__ float s_fb[32], s_gb[32];
    int tid = threadIdx.x;
    {
        const float* fwL = filt_w + layer * 2048;
        const float* gwL = gate_w + layer * 2048;
        for (int e = tid; e < 1024; e += 256) {
            int c = e >> 5, o = e & 31;
            int src = (o * 32 + c) * 2;
            s_fw0[c * 32 + o] = fwL[src];
            s_fw1[c * 32 + o] = fwL[src + 1];
            s_gw0[c * 32 + o] = gwL[src];
            s_gw1[c * 32 + o] = gwL[src + 1];
        }
        if (tid < 32) {
            s_fb[tid] = filt_b[layer * 32 + tid];
            s_gb[tid] = gate_b[layer * 32 + tid];
        }
    }
    __syncthreads();

    int i0 = blockIdx.x * 512 + tid;
    int i1 = i0 + 256;
    bool v0 = (i0 & (T_ - 1)) >= dil;
    bool v1 = (i1 & (T_ - 1)) >= dil;

    float fa0[32], fa1[32], ga0[32], ga1[32];
#pragma unroll
    for (int o = 0; o < 32; o++) { fa0[o] = 0.f; fa1[o] = 0.f; ga0[o] = 0.f; ga1[o] = 0.f; }

#pragma unroll 1
    for (int c = 0; c < 32; c++) {
        const float* hrow = g_h + c * BT_;
        float hc0 = hrow[i0], hc1 = hrow[i1];
        float hp0 = v0 ? hrow[i0 - dil] : 0.f;
        float hp1 = v1 ? hrow[i1 - dil] : 0.f;
        const float* wf0 = s_fw0 + c * 32;
        const float* wf1 = s_fw1 + c * 32;
        const float* wg0 = s_gw0 + c * 32;
        const float* wg1 = s_gw1 + c * 32;
#pragma unroll
        for (int o = 0; o < 32; o++) {
            float f0w = wf0[o], f1w = wf1[o], g0w = wg0[o], g1w = wg1[o];
            fa0[o] = fmaf(f0w, hp0, fa0[o]); fa0[o] = fmaf(f1w, hc0, fa0[o]);
            fa1[o] = fmaf(f0w, hp1, fa1[o]); fa1[o] = fmaf(f1w, hc1, fa1[o]);
            ga0[o] = fmaf(g0w, hp0, ga0[o]); ga0[o] = fmaf(g1w, hc0, ga0[o]);
            ga1[o] = fmaf(g0w, hp1, ga1[o]); ga1[o] = fmaf(g1w, hc1, ga1[o]);
        }
    }

#pragma unroll
    for (int o = 0; o < 32; o++) {
        float fx0 = fa0[o] + s_fb[o];
        float ef0 = __expf(-2.f * fabsf(fx0));
        float th0 = copysignf(__fdividef(1.f - ef0, 1.f + ef0), fx0);
        float sg0 = __fdividef(1.f, 1.f + __expf(-(ga0[o] + s_gb[o])));
        float z0 = rtf(th0 * sg0);

        float fx1 = fa1[o] + s_fb[o];
        float ef1 = __expf(-2.f * fabsf(fx1));
        float th1 = copysignf(__fdividef(1.f - ef1, 1.f + ef1), fx1);
        float sg1 = __fdividef(1.f, 1.f + __expf(-(ga1[o] + s_gb[o])));
        float z1 = rtf(th1 * sg1);

        float* zrow = g_z + ((size_t)layer * 32 + o) * BT_;
        zrow[i0] = z0;
        zrow[i1] = z1;
    }
}

// ---------------- per-layer residual update: h += conv(z, res_w, d) (R1) -----
__global__ __launch_bounds__(256) void k_res(const float* __restrict__ res_w,
                                             const float* __restrict__ res_b,
                                             int layer, int dil) {
    __shared__ float s_w0[1024], s_w1[1024];  // [c][o]
    __shared__ float s_b[32];
    int tid = threadIdx.x;
    {
        const float* wL = res_w + layer * 2048;
        for (int e = tid; e < 1024; e += 256) {
            int c = e >> 5, o = e & 31;
            int src = (o * 32 + c) * 2;
            s_w0[c * 32 + o] = wL[src];
            s_w1[c * 32 + o] = wL[src + 1];
        }
        if (tid < 32) s_b[tid] = res_b[layer * 32 + tid];
    }
    __syncthreads();

    int i0 = blockIdx.x * 512 + tid;
    int i1 = i0 + 256;
    bool v0 = (i0 & (T_ - 1)) >= dil;
    bool v1 = (i1 & (T_ - 1)) >= dil;

    float a0[32], a1[32];
#pragma unroll
    for (int o = 0; o < 32; o++) { a0[o] = 0.f; a1[o] = 0.f; }

#pragma unroll 1
    for (int c = 0; c < 32; c++) {
        const float* zrow = g_z + ((size_t)layer * 32 + c) * BT_;
        float zc0 = zrow[i0], zc1 = zrow[i1];
        float zp0 = v0 ? zrow[i0 - dil] : 0.f;
        float zp1 = v1 ? zrow[i1 - dil] : 0.f;
        const float* w0 = s_w0 + c * 32;
        const float* w1 = s_w1 + c * 32;
#pragma unroll
        for (int o = 0; o < 32; o++) {
            float w0v = w0[o], w1v = w1[o];
            a0[o] = fmaf(w0v, zp0, a0[o]); a0[o] = fmaf(w1v, zc0, a0[o]);
            a1[o] = fmaf(w0v, zp1, a1[o]); a1[o] = fmaf(w1v, zc1, a1[o]);
        }
    }
#pragma unroll
    for (int o = 0; o < 32; o++) {
        float* hrow = g_h + o * BT_;
        hrow[i0] = hrow[i0] + a0[o] + s_b[o];
        hrow[i1] = hrow[i1] + a1[o] + s_b[o];
    }
}

// ================== unified tf32 GEMM (cp.async staged, double buffered) =====
// CTA tile: M=256 x N=128. 8 warps as 4(M)x2(N); warp tile 64x64.
// MODE 0: skip  (K=2560, B = g_z with per-(layer,tap) shift, out=relu->g_skip)
// MODE 1: end1  (K=256,  B = g_skip,                        out=relu->g_out1)
// MODE 2: end2  (K=256,  B = g_out1,                        out=transposed dout)
#define SAS 264
#define SBS 136
#define BUFW 12800

template <int MODE>
__device__ __forceinline__ void stage_step(unsigned* sm, int buf, int s, int t0, int tid) {
    unsigned* sA = sm + buf * BUFW;
    unsigned* sB = sm + buf * BUFW + 32 * SAS;
    const unsigned* asrc = g_wA + (MODE == 0 ? WOFF_SKIP : (MODE == 1 ? WOFF_E1 : WOFF_E2))
                         + (size_t)s * 32 * 256;
    // A: 32 rows x 256 words = 2048 x 16B chunks
#pragma unroll
    for (int i = 0; i < 8; i++) {
        int q = tid + i * 256;
        int row = q >> 6, col = (q & 63) * 4;
        uint32_t dst = (uint32_t)__cvta_generic_to_shared(sA + row * SAS + col);
        CP16(dst, asrc + row * 256 + col);
    }
    if (MODE != 0) {
        const float* gB = (MODE == 1) ? g_skip : g_out1;
#pragma unroll
        for (int i = 0; i < 4; i++) {
            int q = tid + i * 256;
            int row = q >> 5, col = (q & 31) * 4;
            uint32_t dst = (uint32_t)__cvta_generic_to_shared(sB + row * SBS + col);
            CP16(dst, gB + (size_t)(s * 32 + row) * BT_ + t0 + col);
        }
    } else {
        int li = s >> 1, tap = s & 1;
        int d = 1 << (li % LAYERS_);
        int j = tid >> 3, l8 = tid & 7;
        const float* zrow = g_z + ((size_t)li * 32 + j) * BT_;
        if (tap == 1) {
#pragma unroll
            for (int i = 0; i < 4; i++) {
                int q = l8 + i * 8;
                uint32_t dst = (uint32_t)__cvta_generic_to_shared(sB + j * SBS + q * 4);
                CP16(dst, zrow + t0 + q * 4);
            }
        } else {
            int r = (4 - (d & 3)) & 3;
            int t0m = t0 & (T_ - 1);
            if (t0m >= d + 4) {
                const float* src = zrow + t0 - d - r;
#pragma unroll
                for (int i = 0; i < 4; i++) {
                    int q = l8 + i * 8;
                    uint32_t dst = (uint32_t)__cvta_generic_to_shared(sB + j * SBS + q * 4);
                    CP16(dst, src + q * 4);
                }
                if (l8 == 0) {
                    uint32_t dst = (uint32_t)__cvta_generic_to_shared(sB + j * SBS + 128);
                    CP16(dst, src + 128);
                }
            } else {
                // boundary tile: scalar predicated staging (rare)
                for (int t = l8; t < 128; t += 8) {
                    int gm = t0 + t;
                    float v = ((gm & (T_ - 1)) >= d) ? zrow[gm - d] : 0.f;
                    sB[j * SBS + r + t] = __float_as_uint(v);
                }
            }
        }
    }
}

template <int MODE>
__global__ __launch_bounds__(256) void k_gemm(const float* __restrict__ bias,
                                              float* __restrict__ dout) {
    extern __shared__ unsigned sm[];
    constexpr int KS = (MODE == 0) ? 80 : 8;
    int tid = threadIdx.x, warp = tid >> 5, lane = tid & 31;
    int grp = lane >> 2, tig = lane & 3;
    int t0 = blockIdx.x * 128;
    int m_off = (warp >> 1) * 64;
    int n_off = (warp & 1) * 64;

    float acc[4][8][4];
#pragma unroll
    for (int mf = 0; mf < 4; mf++)
#pragma unroll
        for (int nf = 0; nf < 8; nf++)
#pragma unroll
            for (int q = 0; q < 4; q++) acc[mf][nf][q] = 0.f;

    stage_step<MODE>(sm, 0, 0, t0, tid);
    CPCOMMIT();

    int buf = 0;
#pragma unroll 1
    for (int s = 0; s < KS; s++) {
        if (s + 1 < KS) {
            stage_step<MODE>(sm, buf ^ 1, s + 1, t0, tid);
            CPCOMMIT();
            CPWAIT1();
        } else {
            CPWAIT0();
        }
        __syncthreads();

        unsigned* sA = sm + buf * BUFW;
        unsigned* sB = sm + buf * BUFW + 32 * SAS;
        int roff = 0;
        if (MODE == 0 && !(s & 1)) {
            int d = 1 << ((s >> 1) % LAYERS_);
            roff = (4 - (d & 3)) & 3;
        }
#pragma unroll
        for (int kc = 0; kc < 32; kc += 8) {
            unsigned a[4][4], b[8][2];
#pragma unroll
            for (int mf = 0; mf < 4; mf++) {
                int r0 = m_off + mf * 16 + grp;
                a[mf][0] = sA[(kc + tig) * SAS + r0];
                a[mf][1] = sA[(kc + tig) * SAS + r0 + 8];
                a[mf][2] = sA[(kc + tig + 4) * SAS + r0];
                a[mf][3] = sA[(kc + tig + 4) * SAS + r0 + 8];
            }
#pragma unroll
            for (int nf = 0; nf < 8; nf++) {
                int ci = n_off + nf * 8 + grp + roff;
                b[nf][0] = sB[(kc + tig) * SBS + ci];
                b[nf][1] = sB[(kc + tig + 4) * SBS + ci];
            }
#pragma unroll
            for (int mf = 0; mf < 4; mf++)
#pragma unroll
                for (int nf = 0; nf < 8; nf++) mma8(acc[mf][nf], a[mf], b[nf]);
        }
        __syncthreads();
        buf ^= 1;
    }

    const float* bp = (MODE == 0) ? g_skipb : bias;

    if (MODE != 2) {
        float* out = (MODE == 0) ? g_skip : g_out1;
#pragma unroll
        for (int mf = 0; mf < 4; mf++)
#pragma unroll
            for (int nf = 0; nf < 8; nf++) {
                int row0 = m_off + mf * 16 + grp;
                int col = t0 + n_off + nf * 8 + 2 * tig;
                float b0 = bp[row0];
                float b1 = bp[row0 + 8];
                float2 v0 = make_float2(rtf(fmaxf(acc[mf][nf][0] + b0, 0.f)),
                                        rtf(fmaxf(acc[mf][nf][1] + b0, 0.f)));
                float2 v1 = make_float2(rtf(fmaxf(acc[mf][nf][2] + b1, 0.f)),
                                        rtf(fmaxf(acc[mf][nf][3] + b1, 0.f)));
                *(float2*)&out[(size_t)row0 * BT_ + col] = v0;
                *(float2*)&out[(size_t)(row0 + 8) * BT_ + col] = v1;
            }
    } else {
        // transpose 256ch x 128tok -> token-major dout, 64 tokens per half
        float* ts = (float*)sm;  // [64 tok][260]
#pragma unroll 1
        for (int h = 0; h < 2; h++) {
            __syncthreads();
            if ((warp & 1) == h) {
#pragma unroll
                for (int mf = 0; mf < 4; mf++)
#pragma unroll
                    for (int nf = 0; nf < 8; nf++) {
                        int rowL = m_off + mf * 16 + grp;
                        int colL = nf * 8 + 2 * tig;  // 0..63
                        float b0 = bp[rowL];
                        float b1 = bp[rowL + 8];
                        ts[colL * 260 + rowL] = acc[mf][nf][0] + b0;
                        ts[(colL + 1) * 260 + rowL] = acc[mf][nf][1] + b0;
                        ts[colL * 260 + rowL + 8] = acc[mf][nf][2] + b1;
                        ts[(colL + 1) * 260 + rowL + 8] = acc[mf][nf][3] + b1;
                    }
            }
            __syncthreads();
#pragma unroll
            for (int i = 0; i < 16; i++) {
                int q = tid + i * 256;           // 0..4095
                int tk = q >> 6, c4 = (q & 63) * 4;
                float4 v = *(const float4*)&ts[tk * 260 + c4];
                *(float4*)&dout[(size_t)(t0 + h * 64 + tk) * 256 + c4] = v;
            }
        }
    }
}

// ---------------- host launcher ----------------
extern "C" void kernel_launch(void* const* d_in, const int* in_sizes, int n_in,
                              void* d_out, int out_size) {
    const float* x      = (const float*)d_in[0];
    const float* w_in   = (const float*)d_in[1];
    const float* b_in   = (const float*)d_in[2];
    const float* filt_w = (const float*)d_in[3];
    const float* filt_b = (const float*)d_in[4];
    const float* gate_w = (const float*)d_in[5];
    const float* gate_b = (const float*)d_in[6];
    const float* res_w  = (const float*)d_in[7];
    const float* res_b  = (const float*)d_in[8];
    const float* skip_w = (const float*)d_in[9];
    const float* skip_b = (const float*)d_in[10];
    const float* end1_w = (const float*)d_in[11];
    const float* end1_b = (const float*)d_in[12];
    const float* end2_w = (const float*)d_in[13];
    const float* end2_b = (const float*)d_in[14];
    float* out = (float*)d_out;

    const int SMEM = 25600 * 4;  // 102,400 B dynamic
    cudaFuncSetAttribute(k_gemm<0>, cudaFuncAttributeMaxDynamicSharedMemorySize, SMEM);
    cudaFuncSetAttribute(k_gemm<1>, cudaFuncAttributeMaxDynamicSharedMemorySize, SMEM);
    cudaFuncSetAttribute(k_gemm<2>, cudaFuncAttributeMaxDynamicSharedMemorySize, SMEM);

    k_bias<<<1, 256>>>(skip_b);
    k_pack<<<3072, 256>>>(skip_w, end1_w, end2_w);
    k_input<<<BT_ / 512, 256>>>(x, w_in, b_in);

    for (int i = 0; i < NL_; i++) {
        int d = 1 << (i % LAYERS_);
        k_z<<<BT_ / 512, 256>>>(filt_w, filt_b, gate_w, gate_b, i, d);
        k_res<<<BT_ / 512, 256>>>(res_w, res_b, i, d);
    }

    k_gemm<0><<<BT_ / 128, 256, SMEM>>>(nullptr, nullptr);
    k_gemm<1><<<BT_ / 128, 256, SMEM>>>(end1_b, nullptr);
    k_gemm<2><<<BT_ / 128, 256, SMEM>>>(end2_b, out);
}

// round 5
// speedup vs baseline: 1.6516x; 1.1613x over previous
#include <cuda_runtime.h>
#include <cuda_bf16.h>
#include <stdint.h>
#include <math.h>

#define LAYERS_   10
#define NL_       40
#define RC_       32
#define DC_       32
#define SC_       256
#define EC_       256
#define CL_       256
#define B_        8
#define T_        16384
#define BT_       131072   /* B_*T_ */

typedef unsigned long long u64;

// ---------------- scratch (static device globals; no allocations) -------------
__device__ float g_h[32 * BT_];                       // residual state, [c][BT]
__device__ float g_z[167772160];                      // 40*32*BT, [layer][c][BT] (tf32-rounded)
__device__ float g_skip[SC_ * BT_];                   // [c][BT]  relu(skip), tf32-rounded
__device__ float g_out1[EC_ * BT_];                   // [c][BT]  relu(out1), tf32-rounded
__device__ float g_skipb[SC_];
__device__ unsigned g_wA[786432];                     // packed tf32 weights, K-major

#define WOFF_SKIP 0
#define WOFF_E1   655360
#define WOFF_E2   720896

// ---------------- small helpers ----------------
__device__ __forceinline__ unsigned f2tf(float x) {
    unsigned r;
    asm("cvt.rna.tf32.f32 %0, %1;" : "=r"(r) : "f"(x));
    return r;
}
__device__ __forceinline__ float rtf(float x) {      // RN-round to tf32, as float
    return __uint_as_float(f2tf(x));
}
__device__ __forceinline__ void mma8(float* d, const unsigned* a, const unsigned* b) {
    asm volatile(
        "mma.sync.aligned.m16n8k8.row.col.f32.tf32.tf32.f32 "
        "{%0,%1,%2,%3},{%4,%5,%6,%7},{%8,%9},{%0,%1,%2,%3};\n"
        : "+f"(d[0]), "+f"(d[1]), "+f"(d[2]), "+f"(d[3])
        : "r"(a[0]), "r"(a[1]), "r"(a[2]), "r"(a[3]), "r"(b[0]), "r"(b[1]));
}

// packed f32x2 fma: d.lo += a.lo*b.lo ; d.hi += a.hi*b.hi
__device__ __forceinline__ void fma2(u64& d, u64 a, u64 b) {
    asm("fma.rn.f32x2 %0, %1, %2, %0;" : "+l"(d) : "l"(a), "l"(b));
}
__device__ __forceinline__ u64 dup2(float x) {
    u64 r; unsigned xi = __float_as_uint(x);
    asm("mov.b64 %0, {%1, %1};" : "=l"(r) : "r"(xi));
    return r;
}
__device__ __forceinline__ float2 unpk(u64 v) {
    unsigned lo, hi;
    asm("mov.b64 {%0, %1}, %2;" : "=r"(lo), "=r"(hi) : "l"(v));
    return make_float2(__uint_as_float(lo), __uint_as_float(hi));
}
// load 2 adjacent tokens at offset -d with causal zero-padding
__device__ __forceinline__ float2 ld2prev(const float* __restrict__ row, int i0,
                                          int tmod, int d) {
    if (((d & 1) == 0) && tmod >= d) return *(const float2*)(row + (i0 - d));
    float2 r;
    r.x = (tmod >= d) ? row[i0 - d] : 0.f;
    r.y = (tmod + 1 >= d) ? row[i0 + 1 - d] : 0.f;
    return r;
}
__device__ __forceinline__ float act_z(float fx, float gx) {
    float ef = __expf(-2.f * fabsf(fx));
    float th = copysignf(__fdividef(1.f - ef, 1.f + ef), fx);
    float sg = __fdividef(1.f, 1.f + __expf(-gx));
    return rtf(th * sg);
}

#define CP16(dst, src) asm volatile("cp.async.cg.shared.global [%0], [%1], 16;\n" :: "r"(dst), "l"(src))
#define CPCOMMIT()     asm volatile("cp.async.commit_group;\n")
#define CPWAIT1()      asm volatile("cp.async.wait_group 1;\n" ::: "memory")
#define CPWAIT0()      asm volatile("cp.async.wait_group 0;\n" ::: "memory")

// ---------------- bias reduction for skip ----------------
__global__ void k_bias(const float* __restrict__ skip_b) {
    int o = threadIdx.x;
    float s = 0.f;
#pragma unroll 1
    for (int i = 0; i < NL_; i++) s += skip_b[i * SC_ + o];
    g_skipb[o] = s;
}

// ---------------- pack all GEMM weights K-major as tf32 ----------------
__global__ void k_pack(const float* __restrict__ skip_w,
                       const float* __restrict__ e1w,
                       const float* __restrict__ e2w) {
    int idx = blockIdx.x * 256 + threadIdx.x;
    if (idx < WOFF_E1) {
        int k = idx >> 8, m = idx & 255;
        int li = k >> 6, tap = (k >> 5) & 1, c = k & 31;
        g_wA[idx] = f2tf(skip_w[((size_t)(li * 256 + m) * 32 + c) * 2 + tap]);
    } else if (idx < WOFF_E2) {
        int local = idx - WOFF_E1;
        int k = local >> 8, m = local & 255;
        g_wA[idx] = f2tf(e1w[m * 256 + k]);
    } else if (idx < 786432) {
        int local = idx - WOFF_E2;
        int k = local >> 8, m = local & 255;
        g_wA[idx] = f2tf(e2w[m * 256 + k]);
    }
}

// ---------------- input 1x1 conv: x[8,256,16384] -> h[32][BT] ----------------
__global__ __launch_bounds__(256) void k_input(const float* __restrict__ x,
                                               const float* __restrict__ w_in,
                                               const float* __restrict__ b_in) {
    __shared__ float ws[256 * 32];   // [c][rc]
    __shared__ float bs[32];
    int tid = threadIdx.x;
    for (int e = tid; e < 256 * 32; e += 256) {
        int c = e >> 5, rc = e & 31;
        ws[e] = w_in[rc * 256 + c];
    }
    if (tid < 32) bs[tid] = b_in[tid];
    __syncthreads();

    int i0 = blockIdx.x * 512 + tid;
    int i1 = i0 + 256;
    int b0 = i0 >> 14, t0 = i0 & (T_ - 1);
    int b1 = i1 >> 14, t1 = i1 & (T_ - 1);
    const float* x0 = x + (size_t)b0 * 256 * T_ + t0;
    const float* x1 = x + (size_t)b1 * 256 * T_ + t1;

    float a0[32], a1[32];
#pragma unroll
    for (int r = 0; r < 32; r++) { a0[r] = bs[r]; a1[r] = bs[r]; }

#pragma unroll 1
    for (int c = 0; c < 256; c++) {
        float xv0 = x0[(size_t)c * T_];
        float xv1 = x1[(size_t)c * T_];
        const float* w = &ws[c * 32];
#pragma unroll
        for (int r = 0; r < 32; r++) {
            a0[r] = fmaf(w[r], xv0, a0[r]);
            a1[r] = fmaf(w[r], xv1, a1[r]);
        }
    }
#pragma unroll
    for (int r = 0; r < 32; r++) {
        g_h[r * BT_ + i0] = a0[r];
        g_h[r * BT_ + i1] = a1[r];
    }
}

// ---------------- per-layer z = tanh(filt)*sigmoid(gate), f32x2 packed -------
// thread = 2 adjacent tokens x 16 outputs (8 output-pairs, filt+gate)
// block 256 threads: 128 token-slots x 2 output-groups; 256 tokens/block
__global__ __launch_bounds__(256, 2) void k_z(const float* __restrict__ filt_w,
                                              const float* __restrict__ filt_b,
                                              const float* __restrict__ gate_w,
                                              const float* __restrict__ gate_b,
                                              int layer, int dil) {
    __shared__ __align__(16) float s_fw0[1024], s_fw1[1024], s_gw0[1024], s_gw1[1024];
    __shared__ float s_fb[32], s_gb[32];
    int tid = threadIdx.x;
    {
        const float* fwL = filt_w + layer * 2048;
        const float* gwL = gate_w + layer * 2048;
        for (int e = tid; e < 1024; e += 256) {
            int c = e >> 5, o = e & 31;
            int src = (o * 32 + c) * 2;
            s_fw0[c * 32 + o] = fwL[src];
            s_fw1[c * 32 + o] = fwL[src + 1];
            s_gw0[c * 32 + o] = gwL[src];
            s_gw1[c * 32 + o] = gwL[src + 1];
        }
        if (tid < 32) {
            s_fb[tid] = filt_b[layer * 32 + tid];
            s_gb[tid] = gate_b[layer * 32 + tid];
        }
    }
    __syncthreads();

    int og = tid >> 7;          // 0..1
    int slot = tid & 127;
    int ob = og * 16;
    int i0 = blockIdx.x * 256 + slot * 2;
    int tmod = i0 & (T_ - 1);

    u64 fa0[8], fa1[8], ga0[8], ga1[8];
#pragma unroll
    for (int p = 0; p < 8; p++) { fa0[p] = 0; fa1[p] = 0; ga0[p] = 0; ga1[p] = 0; }

    float2 hc = *(const float2*)(g_h + i0);
    float2 hp = ld2prev(g_h, i0, tmod, dil);

#pragma unroll 1
    for (int c = 0; c < 32; c++) {
        int cn = (c < 31) ? c + 1 : 31;
        const float* nrow = g_h + (size_t)cn * BT_;
        float2 nhc = *(const float2*)(nrow + i0);
        float2 nhp = ld2prev(nrow, i0, tmod, dil);

        u64 hcx = dup2(hc.x), hcy = dup2(hc.y);
        u64 hpx = dup2(hp.x), hpy = dup2(hp.y);

        const ulonglong2* wf0 = (const ulonglong2*)&s_fw0[c * 32 + ob];
        const ulonglong2* wf1 = (const ulonglong2*)&s_fw1[c * 32 + ob];
        const ulonglong2* wg0 = (const ulonglong2*)&s_gw0[c * 32 + ob];
        const ulonglong2* wg1 = (const ulonglong2*)&s_gw1[c * 32 + ob];
#pragma unroll
        for (int q = 0; q < 4; q++) {
            ulonglong2 f0 = wf0[q], f1 = wf1[q];
            fma2(fa0[2 * q], f0.x, hpx);     fma2(fa0[2 * q], f1.x, hcx);
            fma2(fa0[2 * q + 1], f0.y, hpx); fma2(fa0[2 * q + 1], f1.y, hcx);
            fma2(fa1[2 * q], f0.x, hpy);     fma2(fa1[2 * q], f1.x, hcy);
            fma2(fa1[2 * q + 1], f0.y, hpy); fma2(fa1[2 * q + 1], f1.y, hcy);
            ulonglong2 g0 = wg0[q], g1 = wg1[q];
            fma2(ga0[2 * q], g0.x, hpx);     fma2(ga0[2 * q], g1.x, hcx);
            fma2(ga0[2 * q + 1], g0.y, hpx); fma2(ga0[2 * q + 1], g1.y, hcx);
            fma2(ga1[2 * q], g0.x, hpy);     fma2(ga1[2 * q], g1.x, hcy);
            fma2(ga1[2 * q + 1], g0.y, hpy); fma2(ga1[2 * q + 1], g1.y, hcy);
        }
        hc = nhc;
        hp = nhp;
    }

    // epilogue: pair p covers outputs (ob+2p, ob+2p+1); fa0=token-lo, fa1=token-hi
#pragma unroll
    for (int p = 0; p < 8; p++) {
        int o0 = ob + 2 * p, o1 = o0 + 1;
        float2 fl = unpk(fa0[p]), fh = unpk(fa1[p]);
        float2 gl = unpk(ga0[p]), gh = unpk(ga1[p]);
        float fb0 = s_fb[o0], fb1 = s_fb[o1], gb0 = s_gb[o0], gb1 = s_gb[o1];
        float2 z0 = make_float2(act_z(fl.x + fb0, gl.x + gb0),
                                act_z(fh.x + fb0, gh.x + gb0));
        float2 z1 = make_float2(act_z(fl.y + fb1, gl.y + gb1),
                                act_z(fh.y + fb1, gh.y + gb1));
        *(float2*)(g_z + ((size_t)layer * 32 + o0) * BT_ + i0) = z0;
        *(float2*)(g_z + ((size_t)layer * 32 + o1) * BT_ + i0) = z1;
    }
}

// ---------------- per-layer residual update, f32x2 packed --------------------
// thread = 2 adjacent tokens x 32 outputs (16 output-pairs); 512 tokens/block
__global__ __launch_bounds__(256, 2) void k_res(const float* __restrict__ res_w,
                                                const float* __restrict__ res_b,
                                                int layer, int dil) {
    __shared__ __align__(16) float s_w0[1024], s_w1[1024];
    __shared__ float s_b[32];
    int tid = threadIdx.x;
    {
        const float* wL = res_w + layer * 2048;
        for (int e = tid; e < 1024; e += 256) {
            int c = e >> 5, o = e & 31;
            int src = (o * 32 + c) * 2;
            s_w0[c * 32 + o] = wL[src];
            s_w1[c * 32 + o] = wL[src + 1];
        }
        if (tid < 32) s_b[tid] = res_b[layer * 32 + tid];
    }
    __syncthreads();

    int i0 = blockIdx.x * 512 + tid * 2;
    int tmod = i0 & (T_ - 1);
    const float* zL = g_z + (size_t)layer * 32 * BT_;

    u64 a0[16], a1[16];
#pragma unroll
    for (int p = 0; p < 16; p++) { a0[p] = 0; a1[p] = 0; }

    float2 zc = *(const float2*)(zL + i0);
    float2 zp = ld2prev(zL, i0, tmod, dil);

#pragma unroll 1
    for (int c = 0; c < 32; c++) {
        int cn = (c < 31) ? c + 1 : 31;
        const float* nrow = zL + (size_t)cn * BT_;
        float2 nzc = *(const float2*)(nrow + i0);
        float2 nzp = ld2prev(nrow, i0, tmod, dil);

        u64 zcx = dup2(zc.x), zcy = dup2(zc.y);
        u64 zpx = dup2(zp.x), zpy = dup2(zp.y);

        const ulonglong2* w0 = (const ulonglong2*)&s_w0[c * 32];
        const ulonglong2* w1 = (const ulonglong2*)&s_w1[c * 32];
#pragma unroll
        for (int q = 0; q < 8; q++) {
            ulonglong2 v0 = w0[q], v1 = w1[q];
            fma2(a0[2 * q], v0.x, zpx);     fma2(a0[2 * q], v1.x, zcx);
            fma2(a0[2 * q + 1], v0.y, zpx); fma2(a0[2 * q + 1], v1.y, zcx);
            fma2(a1[2 * q], v0.x, zpy);     fma2(a1[2 * q], v1.x, zcy);
            fma2(a1[2 * q + 1], v0.y, zpy); fma2(a1[2 * q + 1], v1.y, zcy);
        }
        zc = nzc;
        zp = nzp;
    }

#pragma unroll
    for (int p = 0; p < 16; p++) {
        int o0 = 2 * p, o1 = o0 + 1;
        float2 vl = unpk(a0[p]);  // (o0 lo, o1 lo)
        float2 vh = unpk(a1[p]);  // (o0 hi, o1 hi)
        float b0 = s_b[o0], b1 = s_b[o1];
        float* r0 = g_h + (size_t)o0 * BT_ + i0;
        float* r1 = g_h + (size_t)o1 * BT_ + i0;
        float2 h0 = *(const float2*)r0;
        float2 h1 = *(const float2*)r1;
        h0.x += vl.x + b0; h0.y += vh.x + b0;
        h1.x += vl.y + b1; h1.y += vh.y + b1;
        *(float2*)r0 = h0;
        *(float2*)r1 = h1;
    }
}

// ================== unified tf32 GEMM (cp.async staged, double buffered) =====
#define SAS 264
#define SBS 136
#define BUFW 12800

template <int MODE>
__device__ __forceinline__ void stage_step(unsigned* sm, int buf, int s, int t0, int tid) {
    unsigned* sA = sm + buf * BUFW;
    unsigned* sB = sm + buf * BUFW + 32 * SAS;
    const unsigned* asrc = g_wA + (MODE == 0 ? WOFF_SKIP : (MODE == 1 ? WOFF_E1 : WOFF_E2))
                         + (size_t)s * 32 * 256;
#pragma unroll
    for (int i = 0; i < 8; i++) {
        int q = tid + i * 256;
        int row = q >> 6, col = (q & 63) * 4;
        uint32_t dst = (uint32_t)__cvta_generic_to_shared(sA + row * SAS + col);
        CP16(dst, asrc + row * 256 + col);
    }
    if (MODE != 0) {
        const float* gB = (MODE == 1) ? g_skip : g_out1;
#pragma unroll
        for (int i = 0; i < 4; i++) {
            int q = tid + i * 256;
            int row = q >> 5, col = (q & 31) * 4;
            uint32_t dst = (uint32_t)__cvta_generic_to_shared(sB + row * SBS + col);
            CP16(dst, gB + (size_t)(s * 32 + row) * BT_ + t0 + col);
        }
    } else {
        int li = s >> 1, tap = s & 1;
        int d = 1 << (li % LAYERS_);
        int j = tid >> 3, l8 = tid & 7;
        const float* zrow = g_z + ((size_t)li * 32 + j) * BT_;
        if (tap == 1) {
#pragma unroll
            for (int i = 0; i < 4; i++) {
                int q = l8 + i * 8;
                uint32_t dst = (uint32_t)__cvta_generic_to_shared(sB + j * SBS + q * 4);
                CP16(dst, zrow + t0 + q * 4);
            }
        } else {
            int r = (4 - (d & 3)) & 3;
            int t0m = t0 & (T_ - 1);
            if (t0m >= d + 4) {
                const float* src = zrow + t0 - d - r;
#pragma unroll
                for (int i = 0; i < 4; i++) {
                    int q = l8 + i * 8;
                    uint32_t dst = (uint32_t)__cvta_generic_to_shared(sB + j * SBS + q * 4);
                    CP16(dst, src + q * 4);
                }
                if (l8 == 0) {
                    uint32_t dst = (uint32_t)__cvta_generic_to_shared(sB + j * SBS + 128);
                    CP16(dst, src + 128);
                }
            } else {
                for (int t = l8; t < 128; t += 8) {
                    int gm = t0 + t;
                    float v = ((gm & (T_ - 1)) >= d) ? zrow[gm - d] : 0.f;
                    sB[j * SBS + r + t] = __float_as_uint(v);
                }
            }
        }
    }
}

template <int MODE>
__global__ __launch_bounds__(256) void k_gemm(const float* __restrict__ bias,
                                              float* __restrict__ dout) {
    extern __shared__ unsigned sm[];
    constexpr int KS = (MODE == 0) ? 80 : 8;
    int tid = threadIdx.x, warp = tid >> 5, lane = tid & 31;
    int grp = lane >> 2, tig = lane & 3;
    int t0 = blockIdx.x * 128;
    int m_off = (warp >> 1) * 64;
    int n_off = (warp & 1) * 64;

    float acc[4][8][4];
#pragma unroll
    for (int mf = 0; mf < 4; mf++)
#pragma unroll
        for (int nf = 0; nf < 8; nf++)
#pragma unroll
            for (int q = 0; q < 4; q++) acc[mf][nf][q] = 0.f;

    stage_step<MODE>(sm, 0, 0, t0, tid);
    CPCOMMIT();

    int buf = 0;
#pragma unroll 1
    for (int s = 0; s < KS; s++) {
        if (s + 1 < KS) {
            stage_step<MODE>(sm, buf ^ 1, s + 1, t0, tid);
            CPCOMMIT();
            CPWAIT1();
        } else {
            CPWAIT0();
        }
        __syncthreads();

        unsigned* sA = sm + buf * BUFW;
        unsigned* sB = sm + buf * BUFW + 32 * SAS;
        int roff = 0;
        if (MODE == 0 && !(s & 1)) {
            int d = 1 << ((s >> 1) % LAYERS_);
            roff = (4 - (d & 3)) & 3;
        }
#pragma unroll
        for (int kc = 0; kc < 32; kc += 8) {
            unsigned a[4][4], b[8][2];
#pragma unroll
            for (int mf = 0; mf < 4; mf++) {
                int r0 = m_off + mf * 16 + grp;
                a[mf][0] = sA[(kc + tig) * SAS + r0];
                a[mf][1] = sA[(kc + tig) * SAS + r0 + 8];
                a[mf][2] = sA[(kc + tig + 4) * SAS + r0];
                a[mf][3] = sA[(kc + tig + 4) * SAS + r0 + 8];
            }
#pragma unroll
            for (int nf = 0; nf < 8; nf++) {
                int ci = n_off + nf * 8 + grp + roff;
                b[nf][0] = sB[(kc + tig) * SBS + ci];
                b[nf][1] = sB[(kc + tig + 4) * SBS + ci];
            }
#pragma unroll
            for (int mf = 0; mf < 4; mf++)
#pragma unroll
                for (int nf = 0; nf < 8; nf++) mma8(acc[mf][nf], a[mf], b[nf]);
        }
        __syncthreads();
        buf ^= 1;
    }

    const float* bp = (MODE == 0) ? g_skipb : bias;

    if (MODE != 2) {
        float* out = (MODE == 0) ? g_skip : g_out1;
#pragma unroll
        for (int mf = 0; mf < 4; mf++)
#pragma unroll
            for (int nf = 0; nf < 8; nf++) {
                int row0 = m_off + mf * 16 + grp;
                int col = t0 + n_off + nf * 8 + 2 * tig;
                float b0 = bp[row0];
                float b1 = bp[row0 + 8];
                float2 v0 = make_float2(rtf(fmaxf(acc[mf][nf][0] + b0, 0.f)),
                                        rtf(fmaxf(acc[mf][nf][1] + b0, 0.f)));
                float2 v1 = make_float2(rtf(fmaxf(acc[mf][nf][2] + b1, 0.f)),
                                        rtf(fmaxf(acc[mf][nf][3] + b1, 0.f)));
                *(float2*)&out[(size_t)row0 * BT_ + col] = v0;
                *(float2*)&out[(size_t)(row0 + 8) * BT_ + col] = v1;
            }
    } else {
        float* ts = (float*)sm;  // [64 tok][260]
#pragma unroll 1
        for (int h = 0; h < 2; h++) {
            __syncthreads();
            if ((warp & 1) == h) {
#pragma unroll
                for (int mf = 0; mf < 4; mf++)
#pragma unroll
                    for (int nf = 0; nf < 8; nf++) {
                        int rowL = m_off + mf * 16 + grp;
                        int colL = nf * 8 + 2 * tig;  // 0..63
                        float b0 = bp[rowL];
                        float b1 = bp[rowL + 8];
                        ts[colL * 260 + rowL] = acc[mf][nf][0] + b0;
                        ts[(colL + 1) * 260 + rowL] = acc[mf][nf][1] + b0;
                        ts[colL * 260 + rowL + 8] = acc[mf][nf][2] + b1;
                        ts[(colL + 1) * 260 + rowL + 8] = acc[mf][nf][3] + b1;
                    }
            }
            __syncthreads();
#pragma unroll
            for (int i = 0; i < 16; i++) {
                int q = tid + i * 256;
                int tk = q >> 6, c4 = (q & 63) * 4;
                float4 v = *(const float4*)&ts[tk * 260 + c4];
                *(float4*)&dout[(size_t)(t0 + h * 64 + tk) * 256 + c4] = v;
            }
        }
    }
}

// ---------------- host launcher ----------------
extern "C" void kernel_launch(void* const* d_in, const int* in_sizes, int n_in,
                              void* d_out, int out_size) {
    const float* x      = (const float*)d_in[0];
    const float* w_in   = (const float*)d_in[1];
    const float* b_in   = (const float*)d_in[2];
    const float* filt_w = (const float*)d_in[3];
    const float* filt_b = (const float*)d_in[4];
    const float* gate_w = (const float*)d_in[5];
    const float* gate_b = (const float*)d_in[6];
    const float* res_w  = (const float*)d_in[7];
    const float* res_b  = (const float*)d_in[8];
    const float* skip_w = (const float*)d_in[9];
    const float* skip_b = (const float*)d_in[10];
    const float* end1_w = (const float*)d_in[11];
    const float* end1_b = (const float*)d_in[12];
    const float* end2_w = (const float*)d_in[13];
    const float* end2_b = (const float*)d_in[14];
    float* out = (float*)d_out;

    const int SMEM = 25600 * 4;  // 102,400 B dynamic
    cudaFuncSetAttribute(k_gemm<0>, cudaFuncAttributeMaxDynamicSharedMemorySize, SMEM);
    cudaFuncSetAttribute(k_gemm<1>, cudaFuncAttributeMaxDynamicSharedMemorySize, SMEM);
    cudaFuncSetAttribute(k_gemm<2>, cudaFuncAttributeMaxDynamicSharedMemorySize, SMEM);

    k_bias<<<1, 256>>>(skip_b);
    k_pack<<<3072, 256>>>(skip_w, end1_w, end2_w);
    k_input<<<BT_ / 512, 256>>>(x, w_in, b_in);

    for (int i = 0; i < NL_; i++) {
        int d = 1 << (i % LAYERS_);
        k_z<<<BT_ / 256, 256>>>(filt_w, filt_b, gate_w, gate_b, i, d);
        k_res<<<BT_ / 512, 256>>>(res_w, res_b, i, d);
    }

    k_gemm<0><<<BT_ / 128, 256, SMEM>>>(nullptr, nullptr);
    k_gemm<1><<<BT_ / 128, 256, SMEM>>>(end1_b, nullptr);
    k_gemm<2><<<BT_ / 128, 256, SMEM>>>(end2_b, out);
}